// round 1
// baseline (speedup 1.0000x reference)
#include <cuda_runtime.h>
#include <math.h>

#define Bdim 4096
#define Zdim 256
#define Ydim 64
#define Xdim 30000
#define BN_EPS 1e-3f

// ---------------- device scratch (no allocations allowed) ----------------
__device__ float g_A[Bdim * Zdim];     // A = zs * tmp_L   [B, Z]
__device__ float g_colsum[Xdim];       // sum over batch of h[:,x]
__device__ float g_colsumsq[Xdim];     // sum of squares
__device__ float g_scale[Xdim];        // invstd * gamma
__device__ float g_shift[Xdim];        // beta - mean*invstd*gamma

// ============================================================================
// K0: per batch row b (grid = B, block = 256 = Zdim threads)
//  - y_mu = y @ W_mu^T + b_mu
//  - y_var = softplus(y @ W_var^T + b_var)
//  - zs = softmax(z)
//  - tmp_L = y @ style_L ;  A = zs * tmp_L
//  - also zeroes the BN stat accumulators (covers all X via b*256+t)
// ============================================================================
__global__ __launch_bounds__(256) void k0_small(
    const float* __restrict__ z, const float* __restrict__ y,
    const float* __restrict__ Wmu, const float* __restrict__ bmu,
    const float* __restrict__ Wvar, const float* __restrict__ bvar,
    const float* __restrict__ styleL,
    float* __restrict__ out_mu, float* __restrict__ out_var)
{
    int b = blockIdx.x;
    int t = threadIdx.x;

    __shared__ float ys[Ydim];
    __shared__ float red[256];

    if (t < Ydim) ys[t] = y[b * Ydim + t];

    // zero BN accumulators (graph replays re-run this each launch)
    int gi = b * 256 + t;
    if (gi < Xdim) { g_colsum[gi] = 0.f; g_colsumsq[gi] = 0.f; }

    float zv = z[b * Zdim + t];
    __syncthreads();

    // softmax(z) over Z=256
    red[t] = zv; __syncthreads();
    #pragma unroll
    for (int s = 128; s > 0; s >>= 1) {
        if (t < s) red[t] = fmaxf(red[t], red[t + s]);
        __syncthreads();
    }
    float zmax = red[0]; __syncthreads();
    float e = __expf(zv - zmax);
    red[t] = e; __syncthreads();
    #pragma unroll
    for (int s = 128; s > 0; s >>= 1) {
        if (t < s) red[t] += red[t + s];
        __syncthreads();
    }
    float zs_v = e / red[0];

    // dots over Y=64
    float mu = bmu[t];
    float va = bvar[t];
    float tl = 0.f;
    const float* wm = Wmu  + t * Ydim;
    const float* wv = Wvar + t * Ydim;
    #pragma unroll
    for (int j = 0; j < Ydim; j++) {
        float yj = ys[j];
        mu = fmaf(yj, wm[j], mu);
        va = fmaf(yj, wv[j], va);
        tl = fmaf(yj, styleL[j * Zdim + t], tl);
    }
    out_mu[b * Zdim + t] = mu;
    // softplus, numerically stable
    out_var[b * Zdim + t] = fmaxf(va, 0.f) + log1pf(__expf(-fabsf(va)));
    g_A[b * Zdim + t] = zs_v * tl;
}

// ============================================================================
// K1: h[b,x] = (y @ style_R)[b,x] * (A @ W_g2^T)[b,x]
//  128x128 tile, 256 threads, 8x8 register micro-tile, BK=32.
//  Writes h into outx (the x_rec slice of d_out, used as scratch) and
//  accumulates per-column sum / sumsq for BatchNorm via smem+global atomics.
// ============================================================================
#define BM 128
#define BN 128
#define BK 32

__global__ __launch_bounds__(256, 1) void k1_gemm(
    const float* __restrict__ Wg2,     // [X, Z] row-major
    const float* __restrict__ yall,    // [B, Y]
    const float* __restrict__ styleR,  // [Y, X]
    float* __restrict__ outx)          // [B, X] scratch for h
{
    __shared__ float As[BK][BM];
    __shared__ float Bs[BK][BN];
    __shared__ float s_sum[BN];
    __shared__ float s_sq[BN];

    const int x0 = blockIdx.x * BN;
    const int b0 = blockIdx.y * BM;
    const int t  = threadIdx.x;
    const int tx = t & 15;     // 16 cols of threads
    const int ty = t >> 4;     // 16 rows of threads

    float accC[8][8] = {};
    float accR[8][8] = {};

    if (t < BN) { s_sum[t] = 0.f; s_sq[t] = 0.f; }

    // ---------------- R = y @ style_R   (K = 64) ----------------
    for (int kk = 0; kk < Ydim; kk += BK) {
        __syncthreads();
        // y tile [128 rows b][32 cols k] -> transposed into As[k][m]
        #pragma unroll
        for (int i = 0; i < 4; i++) {
            int f   = t + i * 256;          // float4 index in 128x8
            int row = f >> 3;
            int col = (f & 7) * 4;
            float4 v = *(const float4*)&yall[(b0 + row) * Ydim + kk + col];
            As[col + 0][row] = v.x; As[col + 1][row] = v.y;
            As[col + 2][row] = v.z; As[col + 3][row] = v.w;
        }
        // style_R tile [32 rows j][128 cols x] -> direct into Bs[k][n]
        #pragma unroll
        for (int i = 0; i < 4; i++) {
            int f   = t + i * 256;          // float4 index in 32x32
            int row = f >> 5;
            int col = (f & 31) * 4;
            int x   = x0 + col;
            float4 v = make_float4(0.f, 0.f, 0.f, 0.f);
            if (x < Xdim) v = *(const float4*)&styleR[(kk + row) * Xdim + x];
            *(float4*)&Bs[row][col] = v;
        }
        __syncthreads();
        #pragma unroll
        for (int k = 0; k < BK; k++) {
            float4 a0 = *(const float4*)&As[k][ty * 8];
            float4 a1 = *(const float4*)&As[k][ty * 8 + 4];
            float4 c0 = *(const float4*)&Bs[k][tx * 8];
            float4 c1 = *(const float4*)&Bs[k][tx * 8 + 4];
            float av[8] = {a0.x,a0.y,a0.z,a0.w,a1.x,a1.y,a1.z,a1.w};
            float bv[8] = {c0.x,c0.y,c0.z,c0.w,c1.x,c1.y,c1.z,c1.w};
            #pragma unroll
            for (int i = 0; i < 8; i++)
                #pragma unroll
                for (int j = 0; j < 8; j++)
                    accR[i][j] = fmaf(av[i], bv[j], accR[i][j]);
        }
    }

    // ---------------- C = A @ W_g2^T   (K = 256) ----------------
    for (int kk = 0; kk < Zdim; kk += BK) {
        __syncthreads();
        // A tile [128 b][32 k] stride Z -> transposed into As[k][m]
        #pragma unroll
        for (int i = 0; i < 4; i++) {
            int f   = t + i * 256;
            int row = f >> 3;
            int col = (f & 7) * 4;
            float4 v = *(const float4*)&g_A[(b0 + row) * Zdim + kk + col];
            As[col + 0][row] = v.x; As[col + 1][row] = v.y;
            As[col + 2][row] = v.z; As[col + 3][row] = v.w;
        }
        // W_g2 tile [128 x][32 k] stride Z -> transposed into Bs[k][n]
        #pragma unroll
        for (int i = 0; i < 4; i++) {
            int f   = t + i * 256;
            int row = f >> 3;
            int col = (f & 7) * 4;
            int x   = x0 + row;
            float4 v = make_float4(0.f, 0.f, 0.f, 0.f);
            if (x < Xdim) v = *(const float4*)&Wg2[(size_t)x * Zdim + kk + col];
            Bs[col + 0][row] = v.x; Bs[col + 1][row] = v.y;
            Bs[col + 2][row] = v.z; Bs[col + 3][row] = v.w;
        }
        __syncthreads();
        #pragma unroll
        for (int k = 0; k < BK; k++) {
            float4 a0 = *(const float4*)&As[k][ty * 8];
            float4 a1 = *(const float4*)&As[k][ty * 8 + 4];
            float4 c0 = *(const float4*)&Bs[k][tx * 8];
            float4 c1 = *(const float4*)&Bs[k][tx * 8 + 4];
            float av[8] = {a0.x,a0.y,a0.z,a0.w,a1.x,a1.y,a1.z,a1.w};
            float bv[8] = {c0.x,c0.y,c0.z,c0.w,c1.x,c1.y,c1.z,c1.w};
            #pragma unroll
            for (int i = 0; i < 8; i++)
                #pragma unroll
                for (int j = 0; j < 8; j++)
                    accC[i][j] = fmaf(av[i], bv[j], accC[i][j]);
        }
    }

    // ---------------- epilogue: h = R * C, store + BN partial stats --------
    const bool fullx = (x0 + BN <= Xdim);
    #pragma unroll
    for (int i = 0; i < 8; i++) {
        int b = b0 + ty * 8 + i;
        #pragma unroll
        for (int j = 0; j < 8; j++)
            accC[i][j] *= accR[i][j];

        int xb = x0 + tx * 8;
        float* dst = outx + (size_t)b * Xdim + xb;
        if (fullx) {
            float4 h0 = make_float4(accC[i][0], accC[i][1], accC[i][2], accC[i][3]);
            float4 h1 = make_float4(accC[i][4], accC[i][5], accC[i][6], accC[i][7]);
            *(float4*)dst       = h0;
            *(float4*)(dst + 4) = h1;
        } else {
            #pragma unroll
            for (int j = 0; j < 8; j++)
                if (xb + j < Xdim) dst[j] = accC[i][j];
        }
    }

    #pragma unroll
    for (int j = 0; j < 8; j++) {
        float s = 0.f, q = 0.f;
        #pragma unroll
        for (int i = 0; i < 8; i++) {
            float h = accC[i][j];
            s += h;
            q = fmaf(h, h, q);
        }
        atomicAdd(&s_sum[tx * 8 + j], s);
        atomicAdd(&s_sq [tx * 8 + j], q);
    }
    __syncthreads();
    if (t < BN) {
        int x = x0 + t;
        if (x < Xdim) {
            atomicAdd(&g_colsum[x],   s_sum[t]);
            atomicAdd(&g_colsumsq[x], s_sq[t]);
        }
    }
}

// ============================================================================
// K2: finalize BN affine:  scale = gamma*invstd ; shift = beta - mean*scale
// ============================================================================
__global__ void k2_finalize(const float* __restrict__ gamma,
                            const float* __restrict__ beta)
{
    int x = blockIdx.x * 256 + threadIdx.x;
    if (x >= Xdim) return;
    const float invB = 1.f / (float)Bdim;
    float mean = g_colsum[x] * invB;
    float var  = g_colsumsq[x] * invB - mean * mean;
    float inv  = rsqrtf(var + BN_EPS);
    float sc   = inv * gamma[x];
    g_scale[x] = sc;
    g_shift[x] = beta[x] - mean * sc;
}

// ============================================================================
// K3: per-row: hn = h*scale + shift ; softmax over X=30000, in place.
// Online (m,s) pass, block reduce, then normalize pass.
// ============================================================================
__global__ __launch_bounds__(512) void k3_softmax(float* __restrict__ outx)
{
    int b = blockIdx.x;
    int t = threadIdx.x;
    float* row = outx + (size_t)b * Xdim;

    float m = -1e30f, s = 0.f;
    for (int x = t; x < Xdim; x += 512) {
        float v = fmaf(row[x], g_scale[x], g_shift[x]);
        if (v <= m) {
            s += __expf(v - m);
        } else {
            s = s * __expf(m - v) + 1.f;
            m = v;
        }
    }
    // warp reduce (m, s)
    #pragma unroll
    for (int off = 16; off; off >>= 1) {
        float mo = __shfl_xor_sync(0xFFFFFFFFu, m, off);
        float so = __shfl_xor_sync(0xFFFFFFFFu, s, off);
        float nm = fmaxf(m, mo);
        s = s * __expf(m - nm) + so * __expf(mo - nm);
        m = nm;
    }
    __shared__ float sm[16], ss[16];
    int w = t >> 5, l = t & 31;
    if (l == 0) { sm[w] = m; ss[w] = s; }
    __syncthreads();
    if (w == 0) {
        m = (l < 16) ? sm[l] : -1e30f;
        s = (l < 16) ? ss[l] : 0.f;
        #pragma unroll
        for (int off = 8; off; off >>= 1) {
            float mo = __shfl_xor_sync(0xFFFFFFFFu, m, off);
            float so = __shfl_xor_sync(0xFFFFFFFFu, s, off);
            float nm = fmaxf(m, mo);
            s = s * __expf(m - nm) + so * __expf(mo - nm);
            m = nm;
        }
        if (l == 0) { sm[0] = m; ss[0] = s; }
    }
    __syncthreads();
    float M = sm[0];
    float invS = 1.f / ss[0];

    for (int x = t; x < Xdim; x += 512) {
        float v = fmaf(row[x], g_scale[x], g_shift[x]);
        row[x] = __expf(v - M) * invS;
    }
}

// ============================================================================
extern "C" void kernel_launch(void* const* d_in, const int* in_sizes, int n_in,
                              void* d_out, int out_size)
{
    const float* z      = (const float*)d_in[0];
    const float* y      = (const float*)d_in[1];
    const float* Wmu    = (const float*)d_in[2];
    const float* bmu    = (const float*)d_in[3];
    const float* Wvar   = (const float*)d_in[4];
    const float* bvar   = (const float*)d_in[5];
    const float* Wg2    = (const float*)d_in[6];
    const float* styleL = (const float*)d_in[7];
    const float* styleR = (const float*)d_in[8];
    const float* gamma  = (const float*)d_in[9];
    const float* beta   = (const float*)d_in[10];

    float* out     = (float*)d_out;
    float* out_mu  = out;                       // [B, Z]
    float* out_var = out + (size_t)Bdim * Zdim; // [B, Z]
    float* outx    = out + (size_t)2 * Bdim * Zdim; // [B, X]

    k0_small<<<Bdim, 256>>>(z, y, Wmu, bmu, Wvar, bvar, styleL, out_mu, out_var);

    dim3 g1((Xdim + BN - 1) / BN, Bdim / BM);
    k1_gemm<<<g1, 256>>>(Wg2, y, styleR, outx);

    k2_finalize<<<(Xdim + 255) / 256, 256>>>(gamma, beta);

    k3_softmax<<<Bdim, 512>>>(outx);
}

// round 3
// speedup vs baseline: 1.1927x; 1.1927x over previous
#include <cuda_runtime.h>
#include <cuda_bf16.h>
#include <mma.h>
#include <math.h>
#include <stdint.h>

using namespace nvcuda;

#define Bdim 4096
#define Zdim 256
#define Ydim 64
#define Xdim 30000
#define Xpad 30080
#define BN_EPS 1e-3f

// ---------------- device scratch (bf16 hi/lo splits) ----------------
__device__ __nv_bfloat16 g_Ah[Bdim * Zdim], g_Al[Bdim * Zdim];   // zs*tmp_L
__device__ __nv_bfloat16 g_Wh[Xpad * Zdim], g_Wl[Xpad * Zdim];   // W_g2 (padded X)
__device__ __nv_bfloat16 g_SRh[Ydim * Xpad], g_SRl[Ydim * Xpad]; // style_R
__device__ __nv_bfloat16 g_Yh[Bdim * Ydim], g_Yl[Bdim * Ydim];   // y
__device__ float g_scale[Xdim];
__device__ float g_shift[Xdim];

__device__ __forceinline__ void bsplit(float v, __nv_bfloat16& h, __nv_bfloat16& l) {
    h = __float2bfloat16(v);
    l = __float2bfloat16(v - __bfloat162float(h));
}

// ============================================================================
// Presplit kernels: f32 -> bf16 hi/lo pairs (once per launch, tiny cost)
// ============================================================================
__global__ __launch_bounds__(256) void ksplitW(const float* __restrict__ W) {
    int u = blockIdx.x * 256 + threadIdx.x;          // float4 index
    int x = u >> 6;                                   // 64 float4 per row
    int kg = (u & 63) * 4;
    float4 v = make_float4(0.f, 0.f, 0.f, 0.f);
    if (x < Xdim) v = *(const float4*)&W[(size_t)x * Zdim + kg];
    __nv_bfloat16 h0, h1, h2, h3, l0, l1, l2, l3;
    bsplit(v.x, h0, l0); bsplit(v.y, h1, l1); bsplit(v.z, h2, l2); bsplit(v.w, h3, l3);
    ushort4 ph = make_ushort4(__bfloat16_as_ushort(h0), __bfloat16_as_ushort(h1),
                              __bfloat16_as_ushort(h2), __bfloat16_as_ushort(h3));
    ushort4 pl = make_ushort4(__bfloat16_as_ushort(l0), __bfloat16_as_ushort(l1),
                              __bfloat16_as_ushort(l2), __bfloat16_as_ushort(l3));
    *(ushort4*)&g_Wh[(size_t)u * 4] = ph;
    *(ushort4*)&g_Wl[(size_t)u * 4] = pl;
}

__global__ __launch_bounds__(256) void ksplitSR(const float* __restrict__ SR) {
    int u = blockIdx.x * 256 + threadIdx.x;           // float4 index in padded layout
    int row = u / (Xpad / 4);
    int col = (u % (Xpad / 4)) * 4;
    float4 v = make_float4(0.f, 0.f, 0.f, 0.f);
    if (col < Xdim) v = *(const float4*)&SR[(size_t)row * Xdim + col];
    __nv_bfloat16 h0, h1, h2, h3, l0, l1, l2, l3;
    bsplit(v.x, h0, l0); bsplit(v.y, h1, l1); bsplit(v.z, h2, l2); bsplit(v.w, h3, l3);
    ushort4 ph = make_ushort4(__bfloat16_as_ushort(h0), __bfloat16_as_ushort(h1),
                              __bfloat16_as_ushort(h2), __bfloat16_as_ushort(h3));
    ushort4 pl = make_ushort4(__bfloat16_as_ushort(l0), __bfloat16_as_ushort(l1),
                              __bfloat16_as_ushort(l2), __bfloat16_as_ushort(l3));
    *(ushort4*)&g_SRh[(size_t)row * Xpad + col] = ph;
    *(ushort4*)&g_SRl[(size_t)row * Xpad + col] = pl;
}

__global__ __launch_bounds__(256) void ksplitY(const float* __restrict__ Y) {
    int u = blockIdx.x * 256 + threadIdx.x;           // float4 index
    float4 v = *(const float4*)&Y[(size_t)u * 4];
    __nv_bfloat16 h0, h1, h2, h3, l0, l1, l2, l3;
    bsplit(v.x, h0, l0); bsplit(v.y, h1, l1); bsplit(v.z, h2, l2); bsplit(v.w, h3, l3);
    ushort4 ph = make_ushort4(__bfloat16_as_ushort(h0), __bfloat16_as_ushort(h1),
                              __bfloat16_as_ushort(h2), __bfloat16_as_ushort(h3));
    ushort4 pl = make_ushort4(__bfloat16_as_ushort(l0), __bfloat16_as_ushort(l1),
                              __bfloat16_as_ushort(l2), __bfloat16_as_ushort(l3));
    *(ushort4*)&g_Yh[(size_t)u * 4] = ph;
    *(ushort4*)&g_Yl[(size_t)u * 4] = pl;
}

// ============================================================================
// K0: per batch row — y_mu, y_var, A = zs*tmp_L (split to bf16 hi/lo)
// ============================================================================
__global__ __launch_bounds__(256) void k0_small(
    const float* __restrict__ z, const float* __restrict__ y,
    const float* __restrict__ Wmu, const float* __restrict__ bmu,
    const float* __restrict__ Wvar, const float* __restrict__ bvar,
    const float* __restrict__ styleL,
    float* __restrict__ out_mu, float* __restrict__ out_var)
{
    int b = blockIdx.x;
    int t = threadIdx.x;

    __shared__ float ys[Ydim];
    __shared__ float red[256];

    if (t < Ydim) ys[t] = y[b * Ydim + t];
    float zv = z[b * Zdim + t];
    __syncthreads();

    red[t] = zv; __syncthreads();
    #pragma unroll
    for (int s = 128; s > 0; s >>= 1) {
        if (t < s) red[t] = fmaxf(red[t], red[t + s]);
        __syncthreads();
    }
    float zmax = red[0]; __syncthreads();
    float e = __expf(zv - zmax);
    red[t] = e; __syncthreads();
    #pragma unroll
    for (int s = 128; s > 0; s >>= 1) {
        if (t < s) red[t] += red[t + s];
        __syncthreads();
    }
    float zs_v = e / red[0];

    float mu = bmu[t];
    float va = bvar[t];
    float tl = 0.f;
    const float* wm = Wmu  + t * Ydim;
    const float* wv = Wvar + t * Ydim;
    #pragma unroll
    for (int j = 0; j < Ydim; j++) {
        float yj = ys[j];
        mu = fmaf(yj, wm[j], mu);
        va = fmaf(yj, wv[j], va);
        tl = fmaf(yj, styleL[j * Zdim + t], tl);
    }
    out_mu[b * Zdim + t] = mu;
    out_var[b * Zdim + t] = fmaxf(va, 0.f) + log1pf(__expf(-fabsf(va)));

    float av = zs_v * tl;
    __nv_bfloat16 ah, al;
    bsplit(av, ah, al);
    g_Ah[b * Zdim + t] = ah;
    g_Al[b * Zdim + t] = al;
}

// ============================================================================
// K1: bf16x3 dual GEMM on HMMA (wmma).
//   Tile: M=128 (batch) x N=128 (x). 8 warps, each 64x32.
//   R = y @ style_R (K=64, operands from global)  -> sR smem
//   C = A @ W_g2^T  (K=256, smem-staged, reg-prefetch pipeline)
//   h = C * R -> outx
// ============================================================================
#define LDA 56   // smem row stride in bf16 elems (112B: 16B-aligned, LDSM conflict-free)
#define SM_AH 0
#define SM_AL 14336
#define SM_WH 28672
#define SM_WL 43008
#define SM_R  57344
#define SM_C  122880
#define K1_SMEM 188416

__global__ __launch_bounds__(256) void k1_gemm(float* __restrict__ outx)
{
    extern __shared__ char smem[];
    __nv_bfloat16* sAh = (__nv_bfloat16*)(smem + SM_AH);
    __nv_bfloat16* sAl = (__nv_bfloat16*)(smem + SM_AL);
    __nv_bfloat16* sWh = (__nv_bfloat16*)(smem + SM_WH);
    __nv_bfloat16* sWl = (__nv_bfloat16*)(smem + SM_WL);
    float* sR = (float*)(smem + SM_R);
    float* sC = (float*)(smem + SM_C);

    const int b0 = blockIdx.x * 128;
    const int x0 = blockIdx.y * 128;
    const int t  = threadIdx.x;
    const int wid = t >> 5;
    const int wm = wid & 1;   // 2 warps over M (64 rows each)
    const int wn = wid >> 1;  // 4 warps over N (32 cols each)

    wmma::fragment<wmma::accumulator, 16, 16, 16, float> acc[4][2];

    // ---------------- R = y @ style_R  (K = 64) ----------------
    #pragma unroll
    for (int mi = 0; mi < 4; mi++)
        #pragma unroll
        for (int ni = 0; ni < 2; ni++)
            wmma::fill_fragment(acc[mi][ni], 0.f);

    #pragma unroll
    for (int kk = 0; kk < Ydim; kk += 16) {
        wmma::fragment<wmma::matrix_b, 16, 16, 16, __nv_bfloat16, wmma::row_major> fbh[2], fbl[2];
        #pragma unroll
        for (int ni = 0; ni < 2; ni++) {
            const __nv_bfloat16* bp = g_SRh + (size_t)kk * Xpad + x0 + wn * 32 + ni * 16;
            const __nv_bfloat16* lp = g_SRl + (size_t)kk * Xpad + x0 + wn * 32 + ni * 16;
            wmma::load_matrix_sync(fbh[ni], bp, Xpad);
            wmma::load_matrix_sync(fbl[ni], lp, Xpad);
        }
        #pragma unroll
        for (int mi = 0; mi < 4; mi++) {
            wmma::fragment<wmma::matrix_a, 16, 16, 16, __nv_bfloat16, wmma::row_major> fah, fal;
            const __nv_bfloat16* ap = g_Yh + (size_t)(b0 + wm * 64 + mi * 16) * Ydim + kk;
            const __nv_bfloat16* lp = g_Yl + (size_t)(b0 + wm * 64 + mi * 16) * Ydim + kk;
            wmma::load_matrix_sync(fah, ap, Ydim);
            wmma::load_matrix_sync(fal, lp, Ydim);
            #pragma unroll
            for (int ni = 0; ni < 2; ni++) {
                wmma::mma_sync(acc[mi][ni], fah, fbh[ni], acc[mi][ni]);
                wmma::mma_sync(acc[mi][ni], fah, fbl[ni], acc[mi][ni]);
                wmma::mma_sync(acc[mi][ni], fal, fbh[ni], acc[mi][ni]);
            }
        }
    }
    #pragma unroll
    for (int mi = 0; mi < 4; mi++)
        #pragma unroll
        for (int ni = 0; ni < 2; ni++)
            wmma::store_matrix_sync(&sR[(wm * 64 + mi * 16) * 128 + wn * 32 + ni * 16],
                                    acc[mi][ni], 128, wmma::mem_row_major);

    // ---------------- C = A @ W_g2^T  (K = 256) ----------------
    #pragma unroll
    for (int mi = 0; mi < 4; mi++)
        #pragma unroll
        for (int ni = 0; ni < 2; ni++)
            wmma::fill_fragment(acc[mi][ni], 0.f);

    uint4 pa[4], pw[4];   // prefetch regs: [0,1]=hi, [2,3]=lo

    // load chunk 0
    {
        const int kc = 0;
        #pragma unroll
        for (int i = 0; i < 2; i++) {
            int u = t + i * 256;
            int row = u >> 2;
            int cg = (u & 3) * 8;
            pa[i]     = *(const uint4*)&g_Ah[(size_t)(b0 + row) * Zdim + kc + cg];
            pa[i + 2] = *(const uint4*)&g_Al[(size_t)(b0 + row) * Zdim + kc + cg];
            pw[i]     = *(const uint4*)&g_Wh[(size_t)(x0 + row) * Zdim + kc + cg];
            pw[i + 2] = *(const uint4*)&g_Wl[(size_t)(x0 + row) * Zdim + kc + cg];
        }
    }

    for (int c = 0; c < 8; c++) {
        __syncthreads();
        #pragma unroll
        for (int i = 0; i < 2; i++) {
            int u = t + i * 256;
            int row = u >> 2;
            int cg = (u & 3) * 8;
            *(uint4*)&sAh[row * LDA + cg] = pa[i];
            *(uint4*)&sAl[row * LDA + cg] = pa[i + 2];
            *(uint4*)&sWh[row * LDA + cg] = pw[i];
            *(uint4*)&sWl[row * LDA + cg] = pw[i + 2];
        }
        __syncthreads();

        if (c < 7) {
            const int kc = (c + 1) * 32;
            #pragma unroll
            for (int i = 0; i < 2; i++) {
                int u = t + i * 256;
                int row = u >> 2;
                int cg = (u & 3) * 8;
                pa[i]     = *(const uint4*)&g_Ah[(size_t)(b0 + row) * Zdim + kc + cg];
                pa[i + 2] = *(const uint4*)&g_Al[(size_t)(b0 + row) * Zdim + kc + cg];
                pw[i]     = *(const uint4*)&g_Wh[(size_t)(x0 + row) * Zdim + kc + cg];
                pw[i + 2] = *(const uint4*)&g_Wl[(size_t)(x0 + row) * Zdim + kc + cg];
            }
        }

        #pragma unroll
        for (int k2 = 0; k2 < 32; k2 += 16) {
            wmma::fragment<wmma::matrix_b, 16, 16, 16, __nv_bfloat16, wmma::col_major> fbh[2], fbl[2];
            #pragma unroll
            for (int ni = 0; ni < 2; ni++) {
                wmma::load_matrix_sync(fbh[ni], sWh + (wn * 32 + ni * 16) * LDA + k2, LDA);
                wmma::load_matrix_sync(fbl[ni], sWl + (wn * 32 + ni * 16) * LDA + k2, LDA);
            }
            #pragma unroll
            for (int mi = 0; mi < 4; mi++) {
                wmma::fragment<wmma::matrix_a, 16, 16, 16, __nv_bfloat16, wmma::row_major> fah, fal;
                wmma::load_matrix_sync(fah, sAh + (wm * 64 + mi * 16) * LDA + k2, LDA);
                wmma::load_matrix_sync(fal, sAl + (wm * 64 + mi * 16) * LDA + k2, LDA);
                #pragma unroll
                for (int ni = 0; ni < 2; ni++) {
                    wmma::mma_sync(acc[mi][ni], fah, fbh[ni], acc[mi][ni]);
                    wmma::mma_sync(acc[mi][ni], fah, fbl[ni], acc[mi][ni]);
                    wmma::mma_sync(acc[mi][ni], fal, fbh[ni], acc[mi][ni]);
                }
            }
        }
    }

    // ---------------- epilogue: h = C * R -> global ----------------
    #pragma unroll
    for (int mi = 0; mi < 4; mi++)
        #pragma unroll
        for (int ni = 0; ni < 2; ni++)
            wmma::store_matrix_sync(&sC[(wm * 64 + mi * 16) * 128 + wn * 32 + ni * 16],
                                    acc[mi][ni], 128, wmma::mem_row_major);
    __syncthreads();

    #pragma unroll
    for (int i = 0; i < 16; i++) {
        int u = t + i * 256;
        int row = u >> 5;          // 32 float4 per 128-col row
        int c4 = (u & 31) * 4;
        int x = x0 + c4;
        if (x < Xdim) {
            float4 cv = *(float4*)&sC[row * 128 + c4];
            float4 rv = *(float4*)&sR[row * 128 + c4];
            cv.x *= rv.x; cv.y *= rv.y; cv.z *= rv.z; cv.w *= rv.w;
            *(float4*)&outx[(size_t)(b0 + row) * Xdim + x] = cv;
        }
    }
}

// ============================================================================
// Kstats: column sums over batch -> BN scale/shift
// ============================================================================
__global__ __launch_bounds__(128) void kstats(
    const float* __restrict__ outx,
    const float* __restrict__ gamma, const float* __restrict__ beta)
{
    int x = blockIdx.x * 128 + threadIdx.x;
    if (x >= Xdim) return;
    float s0 = 0.f, s1 = 0.f, s2 = 0.f, s3 = 0.f;
    float q0 = 0.f, q1 = 0.f, q2 = 0.f, q3 = 0.f;
    const float* p = outx + x;
    #pragma unroll 1
    for (int b = 0; b < Bdim; b += 4) {
        float v0 = p[(size_t)(b + 0) * Xdim];
        float v1 = p[(size_t)(b + 1) * Xdim];
        float v2 = p[(size_t)(b + 2) * Xdim];
        float v3 = p[(size_t)(b + 3) * Xdim];
        s0 += v0; q0 = fmaf(v0, v0, q0);
        s1 += v1; q1 = fmaf(v1, v1, q1);
        s2 += v2; q2 = fmaf(v2, v2, q2);
        s3 += v3; q3 = fmaf(v3, v3, q3);
    }
    float s = (s0 + s1) + (s2 + s3);
    float q = (q0 + q1) + (q2 + q3);
    const float invB = 1.f / (float)Bdim;
    float mean = s * invB;
    float var  = q * invB - mean * mean;
    float inv  = rsqrtf(var + BN_EPS);
    float sc   = inv * gamma[x];
    g_scale[x] = sc;
    g_shift[x] = beta[x] - mean * sc;
}

// ============================================================================
// K3: per-row affine + softmax over X, in place
// ============================================================================
__global__ __launch_bounds__(512) void k3_softmax(float* __restrict__ outx)
{
    int b = blockIdx.x;
    int t = threadIdx.x;
    float* row = outx + (size_t)b * Xdim;

    float m = -1e30f, s = 0.f;
    for (int x = t; x < Xdim; x += 512) {
        float v = fmaf(row[x], g_scale[x], g_shift[x]);
        if (v <= m) {
            s += __expf(v - m);
        } else {
            s = s * __expf(m - v) + 1.f;
            m = v;
        }
    }
    #pragma unroll
    for (int off = 16; off; off >>= 1) {
        float mo = __shfl_xor_sync(0xFFFFFFFFu, m, off);
        float so = __shfl_xor_sync(0xFFFFFFFFu, s, off);
        float nm = fmaxf(m, mo);
        s = s * __expf(m - nm) + so * __expf(mo - nm);
        m = nm;
    }
    __shared__ float sm[16], ss[16];
    int w = t >> 5, l = t & 31;
    if (l == 0) { sm[w] = m; ss[w] = s; }
    __syncthreads();
    if (w == 0) {
        m = (l < 16) ? sm[l] : -1e30f;
        s = (l < 16) ? ss[l] : 0.f;
        #pragma unroll
        for (int off = 8; off; off >>= 1) {
            float mo = __shfl_xor_sync(0xFFFFFFFFu, m, off);
            float so = __shfl_xor_sync(0xFFFFFFFFu, s, off);
            float nm = fmaxf(m, mo);
            s = s * __expf(m - nm) + so * __expf(mo - nm);
            m = nm;
        }
        if (l == 0) { sm[0] = m; ss[0] = s; }
    }
    __syncthreads();
    float M = sm[0];
    float invS = 1.f / ss[0];

    for (int x = t; x < Xdim; x += 512) {
        float v = fmaf(row[x], g_scale[x], g_shift[x]);
        row[x] = __expf(v - M) * invS;
    }
}

// ============================================================================
extern "C" void kernel_launch(void* const* d_in, const int* in_sizes, int n_in,
                              void* d_out, int out_size)
{
    const float* z      = (const float*)d_in[0];
    const float* y      = (const float*)d_in[1];
    const float* Wmu    = (const float*)d_in[2];
    const float* bmu    = (const float*)d_in[3];
    const float* Wvar   = (const float*)d_in[4];
    const float* bvar   = (const float*)d_in[5];
    const float* Wg2    = (const float*)d_in[6];
    const float* styleL = (const float*)d_in[7];
    const float* styleR = (const float*)d_in[8];
    const float* gamma  = (const float*)d_in[9];
    const float* beta   = (const float*)d_in[10];

    float* out     = (float*)d_out;
    float* out_mu  = out;
    float* out_var = out + (size_t)Bdim * Zdim;
    float* outx    = out + (size_t)2 * Bdim * Zdim;

    cudaFuncSetAttribute(k1_gemm, cudaFuncAttributeMaxDynamicSharedMemorySize, K1_SMEM);

    ksplitW<<<(Xpad * Zdim / 4 + 255) / 256, 256>>>(Wg2);
    ksplitSR<<<(Ydim * Xpad / 4 + 255) / 256, 256>>>(styleR);
    ksplitY<<<(Bdim * Ydim / 4 + 255) / 256, 256>>>(y);
    k0_small<<<Bdim, 256>>>(z, y, Wmu, bmu, Wvar, bvar, styleL, out_mu, out_var);

    dim3 g1(Bdim / 128, Xpad / 128);
    k1_gemm<<<g1, 256, K1_SMEM>>>(outx);

    kstats<<<(Xdim + 127) / 128, 128>>>(outx, gamma, beta);

    k3_softmax<<<Bdim, 512>>>(outx);
}

// round 5
// speedup vs baseline: 1.9903x; 1.6687x over previous
#include <cuda_runtime.h>
#include <cuda_bf16.h>
#include <mma.h>
#include <math.h>
#include <stdint.h>

using namespace nvcuda;

#define Bdim 4096
#define Zdim 256
#define Ydim 64
#define Xdim 30000
#define Xpad 30080
#define BN_EPS 1e-3f

// ---------------- device scratch ----------------
__device__ __nv_bfloat16 g_Ah[Bdim * Zdim], g_Al[Bdim * Zdim];   // zs*tmp_L
__device__ __nv_bfloat16 g_Wh[Xpad * Zdim], g_Wl[Xpad * Zdim];   // W_g2 (padded X)
__device__ __nv_bfloat16 g_SRh[Ydim * Xpad], g_SRl[Ydim * Xpad]; // style_R
__device__ __nv_bfloat16 g_Yh[Bdim * Ydim], g_Yl[Bdim * Ydim];   // y
__device__ float g_WmuT[Ydim * Zdim], g_WvarT[Ydim * Zdim];      // transposed [Y,Z]
__device__ float g_colsum[Xdim], g_colsumsq[Xdim];
__device__ float g_scale[Xdim], g_shift[Xdim];

__device__ __forceinline__ void bsplit(float v, __nv_bfloat16& h, __nv_bfloat16& l) {
    h = __float2bfloat16(v);
    l = __float2bfloat16(v - __bfloat162float(h));
}

__device__ __forceinline__ uint32_t smem_u32(const void* p) {
    uint32_t a;
    asm("{ .reg .u64 t; cvta.to.shared.u64 t, %1; cvt.u32.u64 %0, t; }" : "=r"(a) : "l"(p));
    return a;
}
#define CP_ASYNC16(dst, src) \
    asm volatile("cp.async.cg.shared.global [%0], [%1], 16;" :: "r"(dst), "l"(src))
#define CP_COMMIT() asm volatile("cp.async.commit_group;")
#define CP_WAIT1()  asm volatile("cp.async.wait_group 1;")
#define CP_WAIT0()  asm volatile("cp.async.wait_group 0;")

// ============================================================================
// ktrans: Wmu/Wvar [Z,Y] -> [Y,Z] (one-time, tiny)
// ============================================================================
__global__ __launch_bounds__(256) void ktrans(const float* __restrict__ Wmu,
                                              const float* __restrict__ Wvar) {
    int j = blockIdx.x, t = threadIdx.x;
    g_WmuT[j * Zdim + t]  = Wmu[t * Ydim + j];
    g_WvarT[j * Zdim + t] = Wvar[t * Ydim + j];
}

// ============================================================================
// Presplit kernels
// ============================================================================
__global__ __launch_bounds__(256) void ksplitW(const float* __restrict__ W) {
    int u = blockIdx.x * 256 + threadIdx.x;          // float4 index
    // piggyback: zero BN accumulators
    if (u < Xdim) { g_colsum[u] = 0.f; g_colsumsq[u] = 0.f; }
    int x = u >> 6;
    int kg = (u & 63) * 4;
    float4 v = make_float4(0.f, 0.f, 0.f, 0.f);
    if (x < Xdim) v = *(const float4*)&W[(size_t)x * Zdim + kg];
    __nv_bfloat16 h0, h1, h2, h3, l0, l1, l2, l3;
    bsplit(v.x, h0, l0); bsplit(v.y, h1, l1); bsplit(v.z, h2, l2); bsplit(v.w, h3, l3);
    *(ushort4*)&g_Wh[(size_t)u * 4] = make_ushort4(__bfloat16_as_ushort(h0), __bfloat16_as_ushort(h1),
                                                   __bfloat16_as_ushort(h2), __bfloat16_as_ushort(h3));
    *(ushort4*)&g_Wl[(size_t)u * 4] = make_ushort4(__bfloat16_as_ushort(l0), __bfloat16_as_ushort(l1),
                                                   __bfloat16_as_ushort(l2), __bfloat16_as_ushort(l3));
}

__global__ __launch_bounds__(256) void ksplitSR(const float* __restrict__ SR) {
    int u = blockIdx.x * 256 + threadIdx.x;
    int row = u / (Xpad / 4);
    int col = (u % (Xpad / 4)) * 4;
    float4 v = make_float4(0.f, 0.f, 0.f, 0.f);
    if (col < Xdim) v = *(const float4*)&SR[(size_t)row * Xdim + col];
    __nv_bfloat16 h0, h1, h2, h3, l0, l1, l2, l3;
    bsplit(v.x, h0, l0); bsplit(v.y, h1, l1); bsplit(v.z, h2, l2); bsplit(v.w, h3, l3);
    *(ushort4*)&g_SRh[(size_t)row * Xpad + col] = make_ushort4(__bfloat16_as_ushort(h0), __bfloat16_as_ushort(h1),
                                                               __bfloat16_as_ushort(h2), __bfloat16_as_ushort(h3));
    *(ushort4*)&g_SRl[(size_t)row * Xpad + col] = make_ushort4(__bfloat16_as_ushort(l0), __bfloat16_as_ushort(l1),
                                                               __bfloat16_as_ushort(l2), __bfloat16_as_ushort(l3));
}

__global__ __launch_bounds__(256) void ksplitY(const float* __restrict__ Y) {
    int u = blockIdx.x * 256 + threadIdx.x;
    float4 v = *(const float4*)&Y[(size_t)u * 4];
    __nv_bfloat16 h0, h1, h2, h3, l0, l1, l2, l3;
    bsplit(v.x, h0, l0); bsplit(v.y, h1, l1); bsplit(v.z, h2, l2); bsplit(v.w, h3, l3);
    *(ushort4*)&g_Yh[(size_t)u * 4] = make_ushort4(__bfloat16_as_ushort(h0), __bfloat16_as_ushort(h1),
                                                   __bfloat16_as_ushort(h2), __bfloat16_as_ushort(h3));
    *(ushort4*)&g_Yl[(size_t)u * 4] = make_ushort4(__bfloat16_as_ushort(l0), __bfloat16_as_ushort(l1),
                                                   __bfloat16_as_ushort(l2), __bfloat16_as_ushort(l3));
}

// ============================================================================
// K0: 8 batch rows per block. Coalesced weight streams ([Y,Z] layout).
// ============================================================================
__global__ __launch_bounds__(256) void k0_small(
    const float* __restrict__ z, const float* __restrict__ y,
    const float* __restrict__ bmu, const float* __restrict__ bvar,
    const float* __restrict__ styleL,
    float* __restrict__ out_mu, float* __restrict__ out_var)
{
    __shared__ float ys[8][Ydim];
    __shared__ float stl[8][Zdim];
    const int b0 = blockIdx.x * 8;
    const int t  = threadIdx.x;

    #pragma unroll
    for (int i = 0; i < 2; i++) {
        int u = t + i * 256;
        ys[u >> 6][u & 63] = y[b0 * Ydim + u];
    }
    __syncthreads();

    float bm = bmu[t], bv = bvar[t];
    float mu[8] = {}, va[8] = {}, tl[8] = {};
    #pragma unroll 4
    for (int j = 0; j < Ydim; j++) {
        float wm = g_WmuT[j * Zdim + t];
        float wv = g_WvarT[j * Zdim + t];
        float sl = styleL[j * Zdim + t];
        #pragma unroll
        for (int r = 0; r < 8; r++) {
            float yj = ys[r][j];
            mu[r] = fmaf(yj, wm, mu[r]);
            va[r] = fmaf(yj, wv, va[r]);
            tl[r] = fmaf(yj, sl, tl[r]);
        }
    }
    #pragma unroll
    for (int r = 0; r < 8; r++) {
        out_mu[(b0 + r) * Zdim + t] = mu[r] + bm;
        float xv = va[r] + bv;
        out_var[(b0 + r) * Zdim + t] = fmaxf(xv, 0.f) + log1pf(__expf(-fabsf(xv)));
        stl[r][t] = tl[r];
    }
    __syncthreads();

    // warp w handles row w: softmax(z) + A
    const int w = t >> 5, l = t & 31;
    const float* zr = z + (size_t)(b0 + w) * Zdim;
    float zv[8];
    float m = -1e30f;
    #pragma unroll
    for (int k = 0; k < 8; k++) { zv[k] = zr[l + 32 * k]; m = fmaxf(m, zv[k]); }
    #pragma unroll
    for (int o = 16; o; o >>= 1) m = fmaxf(m, __shfl_xor_sync(0xFFFFFFFFu, m, o));
    float s = 0.f;
    #pragma unroll
    for (int k = 0; k < 8; k++) { zv[k] = __expf(zv[k] - m); s += zv[k]; }
    #pragma unroll
    for (int o = 16; o; o >>= 1) s += __shfl_xor_sync(0xFFFFFFFFu, s, o);
    float inv = 1.f / s;
    #pragma unroll
    for (int k = 0; k < 8; k++) {
        float a = zv[k] * inv * stl[w][l + 32 * k];
        __nv_bfloat16 ah, al;
        bsplit(a, ah, al);
        int idx = (b0 + w) * Zdim + l + 32 * k;
        g_Ah[idx] = ah;
        g_Al[idx] = al;
    }
}

// ============================================================================
// K1: bf16x3 dual GEMM on HMMA. Tile 128(b) x 128(x), 8 warps (64x32 each).
// ============================================================================
#define LDA 56                 // bf16 elems per smem row (112B)
#define BUF_STRIDE 57344       // 4 matrices x 128 x 56 x 2B
#define OFF_AL 14336
#define OFF_WH 28672
#define OFF_WL 43008
#define K1_SMEM (2 * BUF_STRIDE)

__global__ __launch_bounds__(256, 1) void k1_gemm(float* __restrict__ outx)
{
    extern __shared__ char smem[];
    const int b0 = blockIdx.x * 128;
    const int x0 = blockIdx.y * 128;
    const int t  = threadIdx.x;
    const int wid = t >> 5;
    const int wm = wid & 1;
    const int wn = wid >> 1;

    wmma::fragment<wmma::accumulator, 16, 16, 16, float> accC[4][2], accR[4][2];

    // ---------------- R = y @ style_R  (K = 64) ----------------
    #pragma unroll
    for (int mi = 0; mi < 4; mi++)
        #pragma unroll
        for (int ni = 0; ni < 2; ni++)
            wmma::fill_fragment(accR[mi][ni], 0.f);

    #pragma unroll
    for (int kk = 0; kk < Ydim; kk += 16) {
        wmma::fragment<wmma::matrix_b, 16, 16, 16, __nv_bfloat16, wmma::row_major> fbh[2], fbl[2];
        #pragma unroll
        for (int ni = 0; ni < 2; ni++) {
            wmma::load_matrix_sync(fbh[ni], g_SRh + (size_t)kk * Xpad + x0 + wn * 32 + ni * 16, Xpad);
            wmma::load_matrix_sync(fbl[ni], g_SRl + (size_t)kk * Xpad + x0 + wn * 32 + ni * 16, Xpad);
        }
        #pragma unroll
        for (int mi = 0; mi < 4; mi++) {
            wmma::fragment<wmma::matrix_a, 16, 16, 16, __nv_bfloat16, wmma::row_major> fah, fal;
            wmma::load_matrix_sync(fah, g_Yh + (size_t)(b0 + wm * 64 + mi * 16) * Ydim + kk, Ydim);
            wmma::load_matrix_sync(fal, g_Yl + (size_t)(b0 + wm * 64 + mi * 16) * Ydim + kk, Ydim);
            #pragma unroll
            for (int ni = 0; ni < 2; ni++) {
                wmma::mma_sync(accR[mi][ni], fah, fbh[ni], accR[mi][ni]);
                wmma::mma_sync(accR[mi][ni], fah, fbl[ni], accR[mi][ni]);
                wmma::mma_sync(accR[mi][ni], fal, fbh[ni], accR[mi][ni]);
            }
        }
    }

    // ---------------- C = A @ W_g2^T (K = 256), cp.async pipeline ----------
    #pragma unroll
    for (int mi = 0; mi < 4; mi++)
        #pragma unroll
        for (int ni = 0; ni < 2; ni++)
            wmma::fill_fragment(accC[mi][ni], 0.f);

    const uint32_t sbase = smem_u32(smem);

    auto stage = [&](int c, int p) {
        const int kc = c * 32;
        const uint32_t bb = sbase + p * BUF_STRIDE;
        #pragma unroll
        for (int i = 0; i < 2; i++) {
            int u = t + i * 256;
            int row = u >> 2;
            int cg = (u & 3) * 8;
            uint32_t so = (row * LDA + cg) * 2;
            CP_ASYNC16(bb + so,           &g_Ah[(size_t)(b0 + row) * Zdim + kc + cg]);
            CP_ASYNC16(bb + OFF_AL + so,  &g_Al[(size_t)(b0 + row) * Zdim + kc + cg]);
            CP_ASYNC16(bb + OFF_WH + so,  &g_Wh[(size_t)(x0 + row) * Zdim + kc + cg]);
            CP_ASYNC16(bb + OFF_WL + so,  &g_Wl[(size_t)(x0 + row) * Zdim + kc + cg]);
        }
        CP_COMMIT();
    };

    stage(0, 0);
    for (int c = 0; c < 8; c++) {
        if (c < 7) { stage(c + 1, (c + 1) & 1); CP_WAIT1(); }
        else       { CP_WAIT0(); }
        __syncthreads();

        char* buf = smem + (c & 1) * BUF_STRIDE;
        __nv_bfloat16* sAh = (__nv_bfloat16*)buf;
        __nv_bfloat16* sAl = (__nv_bfloat16*)(buf + OFF_AL);
        __nv_bfloat16* sWh = (__nv_bfloat16*)(buf + OFF_WH);
        __nv_bfloat16* sWl = (__nv_bfloat16*)(buf + OFF_WL);

        #pragma unroll
        for (int k2 = 0; k2 < 32; k2 += 16) {
            wmma::fragment<wmma::matrix_b, 16, 16, 16, __nv_bfloat16, wmma::col_major> fbh[2], fbl[2];
            #pragma unroll
            for (int ni = 0; ni < 2; ni++) {
                wmma::load_matrix_sync(fbh[ni], sWh + (wn * 32 + ni * 16) * LDA + k2, LDA);
                wmma::load_matrix_sync(fbl[ni], sWl + (wn * 32 + ni * 16) * LDA + k2, LDA);
            }
            #pragma unroll
            for (int mi = 0; mi < 4; mi++) {
                wmma::fragment<wmma::matrix_a, 16, 16, 16, __nv_bfloat16, wmma::row_major> fah, fal;
                wmma::load_matrix_sync(fah, sAh + (wm * 64 + mi * 16) * LDA + k2, LDA);
                wmma::load_matrix_sync(fal, sAl + (wm * 64 + mi * 16) * LDA + k2, LDA);
                #pragma unroll
                for (int ni = 0; ni < 2; ni++) {
                    wmma::mma_sync(accC[mi][ni], fah, fbh[ni], accC[mi][ni]);
                    wmma::mma_sync(accC[mi][ni], fah, fbl[ni], accC[mi][ni]);
                    wmma::mma_sync(accC[mi][ni], fal, fbh[ni], accC[mi][ni]);
                }
            }
        }
        __syncthreads();
    }

    // ---------------- epilogue: h = C * R, direct store ----------------
    #pragma unroll
    for (int mi = 0; mi < 4; mi++)
        #pragma unroll
        for (int ni = 0; ni < 2; ni++)
            #pragma unroll
            for (int e = 0; e < accC[mi][ni].num_elements; e++)
                accC[mi][ni].x[e] *= accR[mi][ni].x[e];

    if (x0 + 128 <= Xdim) {
        #pragma unroll
        for (int mi = 0; mi < 4; mi++)
            #pragma unroll
            for (int ni = 0; ni < 2; ni++)
                wmma::store_matrix_sync(
                    &outx[(size_t)(b0 + wm * 64 + mi * 16) * Xdim + x0 + wn * 32 + ni * 16],
                    accC[mi][ni], Xdim, wmma::mem_row_major);
    } else {
        __syncthreads();   // staging smem now reusable as patch
        // NOTE: ldm must be a multiple of 4 for fp32 wmma stores — use 20.
        float* patch = (float*)smem + wid * (16 * 20);
        const int l = t & 31;
        const int pr = l >> 1;
        const int pc = (l & 1) * 8;
        #pragma unroll
        for (int mi = 0; mi < 4; mi++)
            #pragma unroll
            for (int ni = 0; ni < 2; ni++) {
                wmma::store_matrix_sync(patch, accC[mi][ni], 20, wmma::mem_row_major);
                __syncwarp();
                int bb = b0 + wm * 64 + mi * 16 + pr;
                int xb = x0 + wn * 32 + ni * 16 + pc;
                #pragma unroll
                for (int j = 0; j < 8; j++) {
                    int x = xb + j;
                    if (x < Xdim) outx[(size_t)bb * Xdim + x] = patch[pr * 20 + pc + j];
                }
                __syncwarp();
            }
    }
}

// ============================================================================
// Kstats partial: column sum/sumsq over a 512-batch slice, float4, atomics.
// ============================================================================
__global__ __launch_bounds__(128) void kstats_part(const float* __restrict__ outx)
{
    int xq = blockIdx.x * 128 + threadIdx.x;     // float4 index
    if (xq >= Xdim / 4) return;
    int b0 = blockIdx.y * 512;
    const float4* p = (const float4*)outx + xq;
    float4 s0 = make_float4(0, 0, 0, 0), q0 = s0, s1 = s0, q1 = s0;
    #pragma unroll 1
    for (int b = 0; b < 512; b += 2) {
        float4 v0 = p[(size_t)(b0 + b) * (Xdim / 4)];
        float4 v1 = p[(size_t)(b0 + b + 1) * (Xdim / 4)];
        s0.x += v0.x; s0.y += v0.y; s0.z += v0.z; s0.w += v0.w;
        q0.x = fmaf(v0.x, v0.x, q0.x); q0.y = fmaf(v0.y, v0.y, q0.y);
        q0.z = fmaf(v0.z, v0.z, q0.z); q0.w = fmaf(v0.w, v0.w, q0.w);
        s1.x += v1.x; s1.y += v1.y; s1.z += v1.z; s1.w += v1.w;
        q1.x = fmaf(v1.x, v1.x, q1.x); q1.y = fmaf(v1.y, v1.y, q1.y);
        q1.z = fmaf(v1.z, v1.z, q1.z); q1.w = fmaf(v1.w, v1.w, q1.w);
    }
    int x = xq * 4;
    atomicAdd(&g_colsum[x + 0], s0.x + s1.x);
    atomicAdd(&g_colsum[x + 1], s0.y + s1.y);
    atomicAdd(&g_colsum[x + 2], s0.z + s1.z);
    atomicAdd(&g_colsum[x + 3], s0.w + s1.w);
    atomicAdd(&g_colsumsq[x + 0], q0.x + q1.x);
    atomicAdd(&g_colsumsq[x + 1], q0.y + q1.y);
    atomicAdd(&g_colsumsq[x + 2], q0.z + q1.z);
    atomicAdd(&g_colsumsq[x + 3], q0.w + q1.w);
}

__global__ __launch_bounds__(256) void kstats_final(
    const float* __restrict__ gamma, const float* __restrict__ beta)
{
    int x = blockIdx.x * 256 + threadIdx.x;
    if (x >= Xdim) return;
    const float invB = 1.f / (float)Bdim;
    float mean = g_colsum[x] * invB;
    float var  = g_colsumsq[x] * invB - mean * mean;
    float inv  = rsqrtf(var + BN_EPS);
    float sc   = inv * gamma[x];
    g_scale[x] = sc;
    g_shift[x] = beta[x] - mean * sc;
}

// ============================================================================
// K3: per-row affine + softmax over X, in place, float4.
// ============================================================================
__global__ __launch_bounds__(512) void k3_softmax(float* __restrict__ outx)
{
    const int b = blockIdx.x;
    const int t = threadIdx.x;
    float4* row = (float4*)(outx + (size_t)b * Xdim);
    const float4* sc4 = (const float4*)g_scale;
    const float4* sh4 = (const float4*)g_shift;
    const int N4 = Xdim / 4;

    float m = -1e30f, s = 0.f;
    for (int i = t; i < N4; i += 512) {
        float4 v = row[i], sc = sc4[i], sh = sh4[i];
        float a0 = fmaf(v.x, sc.x, sh.x);
        float a1 = fmaf(v.y, sc.y, sh.y);
        float a2 = fmaf(v.z, sc.z, sh.z);
        float a3 = fmaf(v.w, sc.w, sh.w);
        float mv = fmaxf(fmaxf(a0, a1), fmaxf(a2, a3));
        float nm = fmaxf(m, mv);
        s = s * __expf(m - nm) + __expf(a0 - nm) + __expf(a1 - nm)
          + __expf(a2 - nm) + __expf(a3 - nm);
        m = nm;
    }
    #pragma unroll
    for (int o = 16; o; o >>= 1) {
        float mo = __shfl_xor_sync(0xFFFFFFFFu, m, o);
        float so = __shfl_xor_sync(0xFFFFFFFFu, s, o);
        float nm = fmaxf(m, mo);
        s = s * __expf(m - nm) + so * __expf(mo - nm);
        m = nm;
    }
    __shared__ float sm[16], ss[16];
    int w = t >> 5, l = t & 31;
    if (l == 0) { sm[w] = m; ss[w] = s; }
    __syncthreads();
    if (w == 0) {
        m = (l < 16) ? sm[l] : -1e30f;
        s = (l < 16) ? ss[l] : 0.f;
        #pragma unroll
        for (int o = 8; o; o >>= 1) {
            float mo = __shfl_xor_sync(0xFFFFFFFFu, m, o);
            float so = __shfl_xor_sync(0xFFFFFFFFu, s, o);
            float nm = fmaxf(m, mo);
            s = s * __expf(m - nm) + so * __expf(mo - nm);
            m = nm;
        }
        if (l == 0) { sm[0] = m; ss[0] = s; }
    }
    __syncthreads();
    const float M = sm[0];
    const float invS = 1.f / ss[0];

    for (int i = t; i < N4; i += 512) {
        float4 v = row[i], sc = sc4[i], sh = sh4[i];
        float4 o;
        o.x = __expf(fmaf(v.x, sc.x, sh.x) - M) * invS;
        o.y = __expf(fmaf(v.y, sc.y, sh.y) - M) * invS;
        o.z = __expf(fmaf(v.z, sc.z, sh.z) - M) * invS;
        o.w = __expf(fmaf(v.w, sc.w, sh.w) - M) * invS;
        row[i] = o;
    }
}

// ============================================================================
extern "C" void kernel_launch(void* const* d_in, const int* in_sizes, int n_in,
                              void* d_out, int out_size)
{
    const float* z      = (const float*)d_in[0];
    const float* y      = (const float*)d_in[1];
    const float* Wmu    = (const float*)d_in[2];
    const float* bmu    = (const float*)d_in[3];
    const float* Wvar   = (const float*)d_in[4];
    const float* bvar   = (const float*)d_in[5];
    const float* Wg2    = (const float*)d_in[6];
    const float* styleL = (const float*)d_in[7];
    const float* styleR = (const float*)d_in[8];
    const float* gamma  = (const float*)d_in[9];
    const float* beta   = (const float*)d_in[10];

    float* out     = (float*)d_out;
    float* out_mu  = out;
    float* out_var = out + (size_t)Bdim * Zdim;
    float* outx    = out + (size_t)2 * Bdim * Zdim;

    cudaFuncSetAttribute(k1_gemm, cudaFuncAttributeMaxDynamicSharedMemorySize, K1_SMEM);

    ktrans<<<Ydim, 256>>>(Wmu, Wvar);
    ksplitW<<<(Xpad * Zdim / 4 + 255) / 256, 256>>>(Wg2);
    ksplitSR<<<(Ydim * Xpad / 4 + 255) / 256, 256>>>(styleR);
    ksplitY<<<(Bdim * Ydim / 4 + 255) / 256, 256>>>(y);
    k0_small<<<Bdim / 8, 256>>>(z, y, bmu, bvar, styleL, out_mu, out_var);

    dim3 g1(Bdim / 128, Xpad / 128);
    k1_gemm<<<g1, 256, K1_SMEM>>>(outx);

    dim3 gs((Xdim / 4 + 127) / 128, Bdim / 512);
    kstats_part<<<gs, 128>>>(outx);
    kstats_final<<<(Xdim + 255) / 256, 256>>>(gamma, beta);

    k3_softmax<<<Bdim, 512>>>(outx);
}